// round 2
// baseline (speedup 1.0000x reference)
#include <cuda_runtime.h>
#include <cuda_fp16.h>
#include <cstdint>
#include <cstddef>

// Problem sizes
static constexpr int M = 8192;   // tokens
static constexpr int K = 4096;   // in features
static constexpr int N = 4096;   // out features

// GEMM tiling
static constexpr int BM = 128;
static constexpr int BN = 256;
static constexpr int BK = 64;                    // 64 fp16 = 128 B per row
static constexpr int NIT = K / BK;               // 64
static constexpr int STAGES = 4;
static constexpr int A_STAGE_BYTES = BM * 128;   // 16 KB
static constexpr int B_STAGE_BYTES = BN * 128;   // 32 KB
static constexpr int STAGE_BYTES = A_STAGE_BYTES + B_STAGE_BYTES;  // 48 KB
static constexpr int DYN_SMEM = 1024 + STAGES * STAGE_BYTES;       // ~193 KB

// Scratch (static device arrays are allowed; cudaMalloc is not)
__device__ __half g_A[(size_t)M * K];   // sign(x) as fp16, [M,K] row-major
__device__ __half g_B[(size_t)N * K];   // W^T as fp16,     [N,K] row-major (= col-major B)

// ---------------- PTX helpers (baseline sm_103, no 'a' features) ----------------
__device__ __forceinline__ uint32_t smem_u32(const void* p) {
    uint32_t a;
    asm("{ .reg .u64 t; cvta.to.shared.u64 t, %1; cvt.u32.u64 %0, t; }" : "=r"(a) : "l"(p));
    return a;
}
__device__ __forceinline__ void cp_async16(uint32_t s, const void* g) {
    asm volatile("cp.async.cg.shared.global [%0], [%1], 16;" :: "r"(s), "l"(g));
}
__device__ __forceinline__ void cp_commit() {
    asm volatile("cp.async.commit_group;" ::: "memory");
}
template <int NWAIT>
__device__ __forceinline__ void cp_wait() {
    asm volatile("cp.async.wait_group %0;" :: "n"(NWAIT) : "memory");
}
__device__ __forceinline__ void ldsm_x4(uint32_t& r0, uint32_t& r1, uint32_t& r2, uint32_t& r3,
                                        uint32_t addr) {
    asm volatile("ldmatrix.sync.aligned.m8n8.x4.shared.b16 {%0,%1,%2,%3}, [%4];"
                 : "=r"(r0), "=r"(r1), "=r"(r2), "=r"(r3) : "r"(addr));
}
__device__ __forceinline__ void mma16816(float& d0, float& d1, float& d2, float& d3,
                                         uint32_t a0, uint32_t a1, uint32_t a2, uint32_t a3,
                                         uint32_t b0, uint32_t b1) {
    asm volatile(
        "mma.sync.aligned.m16n8k16.row.col.f32.f16.f16.f32 "
        "{%0,%1,%2,%3}, {%4,%5,%6,%7}, {%8,%9}, {%0,%1,%2,%3};"
        : "+f"(d0), "+f"(d1), "+f"(d2), "+f"(d3)
        : "r"(a0), "r"(a1), "r"(a2), "r"(a3), "r"(b0), "r"(b1));
}
// SW128-style swizzle: XOR 16B-chunk index with (row & 7)
__device__ __forceinline__ uint32_t swz(uint32_t off) { return off ^ ((off >> 3) & 0x70); }

// ---------------- Kernel 1: binarize x -> fp16 {+1,-1} ----------------
__global__ void binarize_kernel(const float4* __restrict__ x4, int n4) {
    int i = blockIdx.x * blockDim.x + threadIdx.x;
    const int stride = gridDim.x * blockDim.x;
    const __half one = __float2half_rn(1.0f);
    const __half neg = __float2half_rn(-1.0f);
    uint2* a8 = reinterpret_cast<uint2*>(g_A);
    for (; i < n4; i += stride) {
        float4 v = x4[i];
        __half2 h0 = __halves2half2(v.x > 0.0f ? one : neg, v.y > 0.0f ? one : neg);
        __half2 h1 = __halves2half2(v.z > 0.0f ? one : neg, v.w > 0.0f ? one : neg);
        uint2 pk;
        pk.x = *reinterpret_cast<uint32_t*>(&h0);
        pk.y = *reinterpret_cast<uint32_t*>(&h1);
        a8[i] = pk;
    }
}

// ---------------- Kernel 2: W [K,N] fp32 -> g_B [N,K] fp16 (transpose+convert) ----------------
__global__ void wconv_kernel(const float* __restrict__ W) {
    __shared__ float t[32][33];
    const int n0 = blockIdx.x * 32;
    const int k0 = blockIdx.y * 32;
    const int tx = threadIdx.x, ty = threadIdx.y;   // 32 x 8
#pragma unroll
    for (int r = 0; r < 4; ++r)
        t[ty + 8 * r][tx] = W[(size_t)(k0 + ty + 8 * r) * N + n0 + tx];
    __syncthreads();
#pragma unroll
    for (int r = 0; r < 4; ++r)
        g_B[(size_t)(n0 + ty + 8 * r) * K + k0 + tx] = __float2half_rn(t[tx][ty + 8 * r]);
}

// ---------------- Kernel 3: mma.sync fp16 GEMM + bias ----------------
// CTA 128x256x64, 8 warps (2 M x 4 N), warp tile 64x64.
__device__ __forceinline__ void load_stage(uint32_t tile0, int m0, int n0, int k_it, int slot,
                                           int tid) {
    const int k0 = k_it * BK;
    const uint32_t sa = tile0 + slot * STAGE_BYTES;
    const uint32_t sbm = sa + A_STAGE_BYTES;
    // A: 128 rows x 8 chunks = 1024; B: 256 rows x 8 chunks = 2048; total 3072 / 256 thr = 12 each
#pragma unroll
    for (int c = tid; c < 3072; c += 256) {
        if (c < 1024) {
            const int row = c >> 3, j = c & 7;
            cp_async16(sa + swz((uint32_t)(row * 128 + j * 16)),
                       g_A + (((size_t)(m0 + row)) << 12) + k0 + (j << 3));
        } else {
            const int c2 = c - 1024;
            const int row = c2 >> 3, j = c2 & 7;
            cp_async16(sbm + swz((uint32_t)(row * 128 + j * 16)),
                       g_B + (((size_t)(n0 + row)) << 12) + k0 + (j << 3));
        }
    }
}

__global__ void __launch_bounds__(256, 1) gemm_kernel(float* __restrict__ out,
                                                      const float* __restrict__ bias) {
    extern __shared__ char smem[];
    const uint32_t tile0 = (smem_u32(smem) + 1023) & ~1023u;
    const int tid = threadIdx.x;
    const int wid = tid >> 5;
    const int lane = tid & 31;
    const int m0 = blockIdx.y * BM;
    const int n0 = blockIdx.x * BN;
    const int warp_m = wid & 1;        // 0..1
    const int warp_n = wid >> 1;       // 0..3

    // Lane-relative swizzled ldmatrix offsets (within a stage), for kk=0.
    // A (row-major m16k16 via x4): rows t0-7:m0-7@k0, t8-15:m8-15@k0, t16-23:m0-7@+16B, t24-31:m8-15@+16B
    uint32_t aoff[4];
#pragma unroll
    for (int mi = 0; mi < 4; ++mi) {
        const int row = warp_m * 64 + mi * 16 + (lane & 15);
        const uint32_t kb = (uint32_t)((lane >> 4) << 4);
        aoff[mi] = swz((uint32_t)(row * 128) + kb);
    }
    // B (col-major n16k16 via x4): t0-7:n0-7@k0, t8-15:n0-7@+16B, t16-23:n8-15@k0, t24-31:n8-15@+16B
    uint32_t boff[4];
#pragma unroll
    for (int pj = 0; pj < 4; ++pj) {
        const int row = warp_n * 64 + pj * 16 + (lane & 7) + ((lane >> 4) << 3);
        const uint32_t kb = (uint32_t)(((lane >> 3) & 1) << 4);
        boff[pj] = swz((uint32_t)(row * 128) + kb);
    }

    float acc[4][8][4];
#pragma unroll
    for (int mi = 0; mi < 4; ++mi)
#pragma unroll
        for (int nj = 0; nj < 8; ++nj)
#pragma unroll
            for (int c = 0; c < 4; ++c) acc[mi][nj][c] = 0.0f;

    // Prologue: fill stages 0..2
#pragma unroll
    for (int p = 0; p < STAGES - 1; ++p) {
        load_stage(tile0, m0, n0, p, p, tid);
        cp_commit();
    }

    for (int it = 0; it < NIT; ++it) {
        cp_wait<STAGES - 2>();
        __syncthreads();

        const uint32_t sa = tile0 + (it % STAGES) * STAGE_BYTES;
        const uint32_t sbm = sa + A_STAGE_BYTES;
#pragma unroll
        for (int kk = 0; kk < 4; ++kk) {
            const uint32_t kx = (uint32_t)(kk << 5);   // XOR moves along K inside swizzle
            uint32_t a[4][4];
#pragma unroll
            for (int mi = 0; mi < 4; ++mi)
                ldsm_x4(a[mi][0], a[mi][1], a[mi][2], a[mi][3], sa + (aoff[mi] ^ kx));
            uint32_t b[8][2];
#pragma unroll
            for (int pj = 0; pj < 4; ++pj) {
                uint32_t r0, r1, r2, r3;
                ldsm_x4(r0, r1, r2, r3, sbm + (boff[pj] ^ kx));
                b[pj * 2 + 0][0] = r0; b[pj * 2 + 0][1] = r1;
                b[pj * 2 + 1][0] = r2; b[pj * 2 + 1][1] = r3;
            }
#pragma unroll
            for (int mi = 0; mi < 4; ++mi)
#pragma unroll
                for (int nj = 0; nj < 8; ++nj)
                    mma16816(acc[mi][nj][0], acc[mi][nj][1], acc[mi][nj][2], acc[mi][nj][3],
                             a[mi][0], a[mi][1], a[mi][2], a[mi][3],
                             b[nj][0], b[nj][1]);
        }
        __syncthreads();
        if (it + STAGES - 1 < NIT)
            load_stage(tile0, m0, n0, it + STAGES - 1, (it + STAGES - 1) % STAGES, tid);
        cp_commit();
    }

    // Epilogue: d frag m16n8 layout: c0,c1 -> (row=g, col=tg*2+{0,1}), c2,c3 -> (row=g+8)
    const int g = lane >> 2, tg = lane & 3;
#pragma unroll
    for (int mi = 0; mi < 4; ++mi) {
        const int r0 = m0 + warp_m * 64 + mi * 16 + g;
        float* o0 = out + (size_t)r0 * N;
        float* o1 = out + (size_t)(r0 + 8) * N;
#pragma unroll
        for (int nj = 0; nj < 8; ++nj) {
            const int col = n0 + warp_n * 64 + nj * 8 + tg * 2;
            const float b0 = __ldg(bias + col);
            const float b1 = __ldg(bias + col + 1);
            float2 v0 = make_float2(acc[mi][nj][0] + b0, acc[mi][nj][1] + b1);
            float2 v1 = make_float2(acc[mi][nj][2] + b0, acc[mi][nj][3] + b1);
            *reinterpret_cast<float2*>(o0 + col) = v0;
            *reinterpret_cast<float2*>(o1 + col) = v1;
        }
    }
}

// ---------------- launch ----------------
extern "C" void kernel_launch(void* const* d_in, const int* in_sizes, int n_in,
                              void* d_out, int out_size) {
    const float* x    = (const float*)d_in[0];
    const float* W    = (const float*)d_in[1];
    const float* bias = (const float*)d_in[2];
    float* out = (float*)d_out;

    binarize_kernel<<<4096, 256>>>((const float4*)x, (M * K) / 4);
    wconv_kernel<<<dim3(N / 32, K / 32), dim3(32, 8)>>>(W);

    cudaFuncSetAttribute(gemm_kernel, cudaFuncAttributeMaxDynamicSharedMemorySize, DYN_SMEM);
    gemm_kernel<<<dim3(N / BN, M / BM), 256, DYN_SMEM>>>(out, bias);
}

// round 3
// speedup vs baseline: 1.4499x; 1.4499x over previous
#include <cuda_runtime.h>
#include <cuda_fp16.h>
#include <cstdint>
#include <cstddef>

// Problem sizes
static constexpr int M = 8192;   // tokens
static constexpr int K = 4096;   // in features
static constexpr int N = 4096;   // out features

// GEMM tiling
static constexpr int BM = 128;
static constexpr int BN = 256;
static constexpr int BK = 64;                    // 64 fp16 = 128 B per row
static constexpr int NIT = K / BK;               // 64
static constexpr int STAGES = 4;
static constexpr int A_STAGE_BYTES = BM * 128;   // 16 KB
static constexpr int B_STAGE_BYTES = BN * 128;   // 32 KB
static constexpr int STAGE_BYTES = A_STAGE_BYTES + B_STAGE_BYTES;  // 48 KB
static constexpr int DYN_SMEM = 1024 + STAGES * STAGE_BYTES;       // ~193 KB

// Scratch (static device arrays are allowed; cudaMalloc is not)
__device__ __half g_A[(size_t)M * K];   // sign(x) as fp16, [M,K] row-major
__device__ __half g_B[(size_t)N * K];   // W^T as fp16,     [N,K] row-major (= col-major B)

// ---------------- PTX helpers (baseline sm_103, no 'a' features) ----------------
__device__ __forceinline__ uint32_t smem_u32(const void* p) {
    uint32_t a;
    asm("{ .reg .u64 t; cvta.to.shared.u64 t, %1; cvt.u32.u64 %0, t; }" : "=r"(a) : "l"(p));
    return a;
}
__device__ __forceinline__ void cp_async16(uint32_t s, const void* g) {
    asm volatile("cp.async.cg.shared.global [%0], [%1], 16;" :: "r"(s), "l"(g));
}
__device__ __forceinline__ void cp_commit() {
    asm volatile("cp.async.commit_group;" ::: "memory");
}
template <int NWAIT>
__device__ __forceinline__ void cp_wait() {
    asm volatile("cp.async.wait_group %0;" :: "n"(NWAIT) : "memory");
}
__device__ __forceinline__ void ldsm_x4(uint32_t& r0, uint32_t& r1, uint32_t& r2, uint32_t& r3,
                                        uint32_t addr) {
    asm volatile("ldmatrix.sync.aligned.m8n8.x4.shared.b16 {%0,%1,%2,%3}, [%4];"
                 : "=r"(r0), "=r"(r1), "=r"(r2), "=r"(r3) : "r"(addr));
}
__device__ __forceinline__ void mma16816(float& d0, float& d1, float& d2, float& d3,
                                         uint32_t a0, uint32_t a1, uint32_t a2, uint32_t a3,
                                         uint32_t b0, uint32_t b1) {
    asm volatile(
        "mma.sync.aligned.m16n8k16.row.col.f32.f16.f16.f32 "
        "{%0,%1,%2,%3}, {%4,%5,%6,%7}, {%8,%9}, {%0,%1,%2,%3};"
        : "+f"(d0), "+f"(d1), "+f"(d2), "+f"(d3)
        : "r"(a0), "r"(a1), "r"(a2), "r"(a3), "r"(b0), "r"(b1));
}
// SW128-style swizzle: XOR 16B-chunk index with (row & 7)
__device__ __forceinline__ uint32_t swz(uint32_t off) { return off ^ ((off >> 3) & 0x70); }

// ---------------- Kernel 1: binarize x -> fp16 {+1,-1} ----------------
__global__ void binarize_kernel(const float4* __restrict__ x4, int n4) {
    int i = blockIdx.x * blockDim.x + threadIdx.x;
    const int stride = gridDim.x * blockDim.x;
    const __half one = __float2half_rn(1.0f);
    const __half neg = __float2half_rn(-1.0f);
    uint2* a8 = reinterpret_cast<uint2*>(g_A);
    for (; i < n4; i += stride) {
        float4 v = x4[i];
        __half2 h0 = __halves2half2(v.x > 0.0f ? one : neg, v.y > 0.0f ? one : neg);
        __half2 h1 = __halves2half2(v.z > 0.0f ? one : neg, v.w > 0.0f ? one : neg);
        uint2 pk;
        pk.x = *reinterpret_cast<uint32_t*>(&h0);
        pk.y = *reinterpret_cast<uint32_t*>(&h1);
        a8[i] = pk;
    }
}

// ---------------- Kernel 2: W [K,N] fp32 -> g_B [N,K] fp16 (transpose+convert) ----------------
__global__ void wconv_kernel(const float* __restrict__ W) {
    __shared__ float t[32][33];
    const int n0 = blockIdx.x * 32;
    const int k0 = blockIdx.y * 32;
    const int tx = threadIdx.x, ty = threadIdx.y;   // 32 x 8
#pragma unroll
    for (int r = 0; r < 4; ++r)
        t[ty + 8 * r][tx] = W[(size_t)(k0 + ty + 8 * r) * N + n0 + tx];
    __syncthreads();
#pragma unroll
    for (int r = 0; r < 4; ++r)
        g_B[(size_t)(n0 + ty + 8 * r) * K + k0 + tx] = __float2half_rn(t[tx][ty + 8 * r]);
}

// ---------------- Kernel 3: mma.sync fp16 GEMM + bias ----------------
// CTA 128x256x64, 8 warps (2 M x 4 N), warp tile 64x64.
// One barrier per k-iter; cp.async issued BEFORE compute; register double-buffered frags.
__device__ __forceinline__ void load_stage(uint32_t tile0, int m0, int n0, int k_it, int slot,
                                           int tid) {
    const int k0 = k_it * BK;
    const uint32_t sa = tile0 + slot * STAGE_BYTES;
    const uint32_t sbm = sa + A_STAGE_BYTES;
    // A: 128 rows x 8 chunks = 1024; B: 256 rows x 8 chunks = 2048; total 3072 / 256 thr = 12 each
#pragma unroll
    for (int c = tid; c < 3072; c += 256) {
        if (c < 1024) {
            const int row = c >> 3, j = c & 7;
            cp_async16(sa + swz((uint32_t)(row * 128 + j * 16)),
                       g_A + (((size_t)(m0 + row)) << 12) + k0 + (j << 3));
        } else {
            const int c2 = c - 1024;
            const int row = c2 >> 3, j = c2 & 7;
            cp_async16(sbm + swz((uint32_t)(row * 128 + j * 16)),
                       g_B + (((size_t)(n0 + row)) << 12) + k0 + (j << 3));
        }
    }
}

__global__ void __launch_bounds__(256, 1) gemm_kernel(float* __restrict__ out,
                                                      const float* __restrict__ bias) {
    extern __shared__ char smem[];
    const uint32_t tile0 = (smem_u32(smem) + 1023) & ~1023u;
    const int tid = threadIdx.x;
    const int wid = tid >> 5;
    const int lane = tid & 31;
    const int m0 = blockIdx.y * BM;
    const int n0 = blockIdx.x * BN;
    const int warp_m = wid & 1;        // 0..1
    const int warp_n = wid >> 1;       // 0..3

    // Lane-relative swizzled ldmatrix offsets (within a stage), for kk=0.
    uint32_t aoff[4];
#pragma unroll
    for (int mi = 0; mi < 4; ++mi) {
        const int row = warp_m * 64 + mi * 16 + (lane & 15);
        const uint32_t kb = (uint32_t)((lane >> 4) << 4);
        aoff[mi] = swz((uint32_t)(row * 128) + kb);
    }
    uint32_t boff[4];
#pragma unroll
    for (int pj = 0; pj < 4; ++pj) {
        const int row = warp_n * 64 + pj * 16 + (lane & 7) + ((lane >> 4) << 3);
        const uint32_t kb = (uint32_t)(((lane >> 3) & 1) << 4);
        boff[pj] = swz((uint32_t)(row * 128) + kb);
    }

    float acc[4][8][4];
#pragma unroll
    for (int mi = 0; mi < 4; ++mi)
#pragma unroll
        for (int nj = 0; nj < 8; ++nj)
#pragma unroll
            for (int c = 0; c < 4; ++c) acc[mi][nj][c] = 0.0f;

    // Prologue: fill stages 0..2
#pragma unroll
    for (int p = 0; p < STAGES - 1; ++p) {
        load_stage(tile0, m0, n0, p, p, tid);
        cp_commit();
    }

    uint32_t afr[2][4][4];   // [buf][mi][frag]
    uint32_t bfr[2][8][2];   // [buf][nj][frag]

    for (int it = 0; it < NIT; ++it) {
        cp_wait<STAGES - 2>();
        __syncthreads();   // all reads of slot (it-1)%4 are done; stage `it` is resident

        // Issue next stage's loads FIRST so they overlap this iter's compute.
        if (it + STAGES - 1 < NIT)
            load_stage(tile0, m0, n0, it + STAGES - 1, (it + STAGES - 1) % STAGES, tid);
        cp_commit();

        const uint32_t sa = tile0 + (it % STAGES) * STAGE_BYTES;
        const uint32_t sbm = sa + A_STAGE_BYTES;

        // Preload kk=0 fragments
#pragma unroll
        for (int mi = 0; mi < 4; ++mi)
            ldsm_x4(afr[0][mi][0], afr[0][mi][1], afr[0][mi][2], afr[0][mi][3], sa + aoff[mi]);
#pragma unroll
        for (int pj = 0; pj < 4; ++pj) {
            uint32_t r0, r1, r2, r3;
            ldsm_x4(r0, r1, r2, r3, sbm + boff[pj]);
            bfr[0][pj * 2 + 0][0] = r0; bfr[0][pj * 2 + 0][1] = r1;
            bfr[0][pj * 2 + 1][0] = r2; bfr[0][pj * 2 + 1][1] = r3;
        }

#pragma unroll
        for (int kk = 0; kk < 4; ++kk) {
            const int cur = kk & 1, nxt = cur ^ 1;
            if (kk < 3) {
                const uint32_t kx = (uint32_t)((kk + 1) << 5);
#pragma unroll
                for (int mi = 0; mi < 4; ++mi)
                    ldsm_x4(afr[nxt][mi][0], afr[nxt][mi][1], afr[nxt][mi][2], afr[nxt][mi][3],
                            sa + (aoff[mi] ^ kx));
#pragma unroll
                for (int pj = 0; pj < 4; ++pj) {
                    uint32_t r0, r1, r2, r3;
                    ldsm_x4(r0, r1, r2, r3, sbm + (boff[pj] ^ kx));
                    bfr[nxt][pj * 2 + 0][0] = r0; bfr[nxt][pj * 2 + 0][1] = r1;
                    bfr[nxt][pj * 2 + 1][0] = r2; bfr[nxt][pj * 2 + 1][1] = r3;
                }
            }
#pragma unroll
            for (int mi = 0; mi < 4; ++mi)
#pragma unroll
                for (int nj = 0; nj < 8; ++nj)
                    mma16816(acc[mi][nj][0], acc[mi][nj][1], acc[mi][nj][2], acc[mi][nj][3],
                             afr[cur][mi][0], afr[cur][mi][1], afr[cur][mi][2], afr[cur][mi][3],
                             bfr[cur][nj][0], bfr[cur][nj][1]);
        }
    }

    // Epilogue: d frag m16n8 layout: c0,c1 -> (row=g, col=tg*2+{0,1}), c2,c3 -> (row=g+8)
    const int g = lane >> 2, tg = lane & 3;
#pragma unroll
    for (int mi = 0; mi < 4; ++mi) {
        const int r0 = m0 + warp_m * 64 + mi * 16 + g;
        float* o0 = out + (size_t)r0 * N;
        float* o1 = out + (size_t)(r0 + 8) * N;
#pragma unroll
        for (int nj = 0; nj < 8; ++nj) {
            const int col = n0 + warp_n * 64 + nj * 8 + tg * 2;
            const float b0 = __ldg(bias + col);
            const float b1 = __ldg(bias + col + 1);
            float2 v0 = make_float2(acc[mi][nj][0] + b0, acc[mi][nj][1] + b1);
            float2 v1 = make_float2(acc[mi][nj][2] + b0, acc[mi][nj][3] + b1);
            *reinterpret_cast<float2*>(o0 + col) = v0;
            *reinterpret_cast<float2*>(o1 + col) = v1;
        }
    }
}

// ---------------- launch ----------------
extern "C" void kernel_launch(void* const* d_in, const int* in_sizes, int n_in,
                              void* d_out, int out_size) {
    const float* x    = (const float*)d_in[0];
    const float* W    = (const float*)d_in[1];
    const float* bias = (const float*)d_in[2];
    float* out = (float*)d_out;

    binarize_kernel<<<4096, 256>>>((const float4*)x, (M * K) / 4);
    wconv_kernel<<<dim3(N / 32, K / 32), dim3(32, 8)>>>(W);

    cudaFuncSetAttribute(gemm_kernel, cudaFuncAttributeMaxDynamicSharedMemorySize, DYN_SMEM);
    gemm_kernel<<<dim3(N / BN, M / BM), 256, DYN_SMEM>>>(out, bias);
}

// round 4
// speedup vs baseline: 1.4501x; 1.0002x over previous
#include <cuda_runtime.h>
#include <cuda_fp16.h>
#include <cstdint>
#include <cstddef>

// Problem sizes
static constexpr int M = 8192;   // tokens
static constexpr int K = 4096;   // in features
static constexpr int N = 4096;   // out features

// GEMM tiling: CTA 128x128x64, 8 warps (2 M x 4 N), warp tile 64x32. 2 CTAs/SM.
static constexpr int BM = 128;
static constexpr int BN = 128;
static constexpr int BK = 64;                    // 64 fp16 = 128 B per row
static constexpr int NIT = K / BK;               // 64
static constexpr int STAGES = 3;
static constexpr int A_STAGE_BYTES = BM * 128;   // 16 KB
static constexpr int B_STAGE_BYTES = BN * 128;   // 16 KB
static constexpr int STAGE_BYTES = A_STAGE_BYTES + B_STAGE_BYTES;  // 32 KB
static constexpr int DYN_SMEM = 1024 + STAGES * STAGE_BYTES;       // ~97 KB -> 2 CTAs/SM

// Scratch (static device arrays are allowed; cudaMalloc is not)
__device__ __half g_A[(size_t)M * K];   // sign(x) as fp16, [M,K] row-major
__device__ __half g_B[(size_t)N * K];   // W^T as fp16,     [N,K] row-major (= col-major B)

// ---------------- PTX helpers (baseline sm_103, no 'a' features) ----------------
__device__ __forceinline__ uint32_t smem_u32(const void* p) {
    uint32_t a;
    asm("{ .reg .u64 t; cvta.to.shared.u64 t, %1; cvt.u32.u64 %0, t; }" : "=r"(a) : "l"(p));
    return a;
}
__device__ __forceinline__ void cp_async16(uint32_t s, const void* g) {
    asm volatile("cp.async.cg.shared.global [%0], [%1], 16;" :: "r"(s), "l"(g));
}
__device__ __forceinline__ void cp_commit() {
    asm volatile("cp.async.commit_group;" ::: "memory");
}
template <int NWAIT>
__device__ __forceinline__ void cp_wait() {
    asm volatile("cp.async.wait_group %0;" :: "n"(NWAIT) : "memory");
}
__device__ __forceinline__ void ldsm_x4(uint32_t& r0, uint32_t& r1, uint32_t& r2, uint32_t& r3,
                                        uint32_t addr) {
    asm volatile("ldmatrix.sync.aligned.m8n8.x4.shared.b16 {%0,%1,%2,%3}, [%4];"
                 : "=r"(r0), "=r"(r1), "=r"(r2), "=r"(r3) : "r"(addr));
}
__device__ __forceinline__ void mma16816(float& d0, float& d1, float& d2, float& d3,
                                         uint32_t a0, uint32_t a1, uint32_t a2, uint32_t a3,
                                         uint32_t b0, uint32_t b1) {
    asm volatile(
        "mma.sync.aligned.m16n8k16.row.col.f32.f16.f16.f32 "
        "{%0,%1,%2,%3}, {%4,%5,%6,%7}, {%8,%9}, {%0,%1,%2,%3};"
        : "+f"(d0), "+f"(d1), "+f"(d2), "+f"(d3)
        : "r"(a0), "r"(a1), "r"(a2), "r"(a3), "r"(b0), "r"(b1));
}
// SW128-style swizzle: XOR 16B-chunk index with (row & 7)
__device__ __forceinline__ uint32_t swz(uint32_t off) { return off ^ ((off >> 3) & 0x70); }

// ---------------- Kernel 1: binarize x -> fp16 {+1,-1} ----------------
__global__ void binarize_kernel(const float4* __restrict__ x4, int n4) {
    int i = blockIdx.x * blockDim.x + threadIdx.x;
    const int stride = gridDim.x * blockDim.x;
    const __half one = __float2half_rn(1.0f);
    const __half neg = __float2half_rn(-1.0f);
    uint2* a8 = reinterpret_cast<uint2*>(g_A);
    for (; i < n4; i += stride) {
        float4 v = x4[i];
        __half2 h0 = __halves2half2(v.x > 0.0f ? one : neg, v.y > 0.0f ? one : neg);
        __half2 h1 = __halves2half2(v.z > 0.0f ? one : neg, v.w > 0.0f ? one : neg);
        uint2 pk;
        pk.x = *reinterpret_cast<uint32_t*>(&h0);
        pk.y = *reinterpret_cast<uint32_t*>(&h1);
        a8[i] = pk;
    }
}

// ---------------- Kernel 2: W [K,N] fp32 -> g_B [N,K] fp16 (transpose+convert) ----------------
__global__ void wconv_kernel(const float* __restrict__ W) {
    __shared__ float t[32][33];
    const int n0 = blockIdx.x * 32;
    const int k0 = blockIdx.y * 32;
    const int tx = threadIdx.x, ty = threadIdx.y;   // 32 x 8
#pragma unroll
    for (int r = 0; r < 4; ++r)
        t[ty + 8 * r][tx] = W[(size_t)(k0 + ty + 8 * r) * N + n0 + tx];
    __syncthreads();
#pragma unroll
    for (int r = 0; r < 4; ++r)
        g_B[(size_t)(n0 + ty + 8 * r) * K + k0 + tx] = __float2half_rn(t[tx][ty + 8 * r]);
}

// ---------------- Kernel 3: mma.sync fp16 GEMM + bias ----------------
__device__ __forceinline__ void load_stage(uint32_t tile0, int m0, int n0, int k_it, int slot,
                                           int tid) {
    const int k0 = k_it * BK;
    const uint32_t sa = tile0 + slot * STAGE_BYTES;
    const uint32_t sbm = sa + A_STAGE_BYTES;
    // A: 128 rows x 8 chunks = 1024; B: 128 rows x 8 chunks = 1024; 2048 / 256 thr = 8 each
#pragma unroll
    for (int c = tid; c < 2048; c += 256) {
        const int r = (c & 1023) >> 3, j = c & 7;
        const uint32_t so = swz((uint32_t)(r * 128 + j * 16));
        if (c < 1024)
            cp_async16(sa + so, g_A + (((size_t)(m0 + r)) << 12) + k0 + (j << 3));
        else
            cp_async16(sbm + so, g_B + (((size_t)(n0 + r)) << 12) + k0 + (j << 3));
    }
}

__global__ void __launch_bounds__(256, 2) gemm_kernel(float* __restrict__ out,
                                                      const float* __restrict__ bias) {
    extern __shared__ char smem[];
    const uint32_t tile0 = (smem_u32(smem) + 1023) & ~1023u;
    const int tid = threadIdx.x;
    const int wid = tid >> 5;
    const int lane = tid & 31;
    const int m0 = blockIdx.y * BM;
    const int n0 = blockIdx.x * BN;
    const int warp_m = wid & 1;        // 0..1 -> 64 rows
    const int warp_n = wid >> 1;       // 0..3 -> 32 cols

    // Swizzled ldmatrix offsets (kk=0).
    // A row-major m16k16 x4: t0-7 m0-7@k0, t8-15 m8-15@k0, t16-23 m0-7@+16B, t24-31 m8-15@+16B
    uint32_t aoff[4];
#pragma unroll
    for (int mi = 0; mi < 4; ++mi) {
        const int row = warp_m * 64 + mi * 16 + (lane & 15);
        aoff[mi] = swz((uint32_t)(row * 128) + (uint32_t)((lane >> 4) << 4));
    }
    // B col-major n16k16 x4: t0-7 n0-7@k0, t8-15 n0-7@+16B, t16-23 n8-15@k0, t24-31 n8-15@+16B
    uint32_t boff[2];
#pragma unroll
    for (int pj = 0; pj < 2; ++pj) {
        const int row = warp_n * 32 + pj * 16 + (lane & 7) + ((lane >> 4) << 3);
        boff[pj] = swz((uint32_t)(row * 128) + (uint32_t)(((lane >> 3) & 1) << 4));
    }

    float acc[4][4][4];   // [mi][nj][c]
#pragma unroll
    for (int mi = 0; mi < 4; ++mi)
#pragma unroll
        for (int nj = 0; nj < 4; ++nj)
#pragma unroll
            for (int c = 0; c < 4; ++c) acc[mi][nj][c] = 0.0f;

    // Prologue: fill stages 0..1
#pragma unroll
    for (int p = 0; p < STAGES - 1; ++p) {
        load_stage(tile0, m0, n0, p, p, tid);
        cp_commit();
    }

    for (int it = 0; it < NIT; ++it) {
        cp_wait<STAGES - 2>();
        __syncthreads();

        // Issue next stage's loads first so they overlap this iter's compute.
        if (it + STAGES - 1 < NIT)
            load_stage(tile0, m0, n0, it + STAGES - 1, (it + STAGES - 1) % STAGES, tid);
        cp_commit();

        const uint32_t sa = tile0 + (it % STAGES) * STAGE_BYTES;
        const uint32_t sbm = sa + A_STAGE_BYTES;

#pragma unroll
        for (int kk = 0; kk < 4; ++kk) {
            const uint32_t kx = (uint32_t)(kk << 5);
            uint32_t a[4][4];
#pragma unroll
            for (int mi = 0; mi < 4; ++mi)
                ldsm_x4(a[mi][0], a[mi][1], a[mi][2], a[mi][3], sa + (aoff[mi] ^ kx));
            uint32_t b[4][2];
#pragma unroll
            for (int pj = 0; pj < 2; ++pj) {
                uint32_t r0, r1, r2, r3;
                ldsm_x4(r0, r1, r2, r3, sbm + (boff[pj] ^ kx));
                b[pj * 2 + 0][0] = r0; b[pj * 2 + 0][1] = r1;
                b[pj * 2 + 1][0] = r2; b[pj * 2 + 1][1] = r3;
            }
#pragma unroll
            for (int mi = 0; mi < 4; ++mi)
#pragma unroll
                for (int nj = 0; nj < 4; ++nj)
                    mma16816(acc[mi][nj][0], acc[mi][nj][1], acc[mi][nj][2], acc[mi][nj][3],
                             a[mi][0], a[mi][1], a[mi][2], a[mi][3],
                             b[nj][0], b[nj][1]);
        }
    }

    // Epilogue
    const int g = lane >> 2, tg = lane & 3;
#pragma unroll
    for (int mi = 0; mi < 4; ++mi) {
        const int r0 = m0 + warp_m * 64 + mi * 16 + g;
        float* o0 = out + (size_t)r0 * N;
        float* o1 = out + (size_t)(r0 + 8) * N;
#pragma unroll
        for (int nj = 0; nj < 4; ++nj) {
            const int col = n0 + warp_n * 32 + nj * 8 + tg * 2;
            const float b0 = __ldg(bias + col);
            const float b1 = __ldg(bias + col + 1);
            float2 v0 = make_float2(acc[mi][nj][0] + b0, acc[mi][nj][1] + b1);
            float2 v1 = make_float2(acc[mi][nj][2] + b0, acc[mi][nj][3] + b1);
            *reinterpret_cast<float2*>(o0 + col) = v0;
            *reinterpret_cast<float2*>(o1 + col) = v1;
        }
    }
}

// ---------------- launch ----------------
extern "C" void kernel_launch(void* const* d_in, const int* in_sizes, int n_in,
                              void* d_out, int out_size) {
    const float* x    = (const float*)d_in[0];
    const float* W    = (const float*)d_in[1];
    const float* bias = (const float*)d_in[2];
    float* out = (float*)d_out;

    binarize_kernel<<<4096, 256>>>((const float4*)x, (M * K) / 4);
    wconv_kernel<<<dim3(N / 32, K / 32), dim3(32, 8)>>>(W);

    cudaFuncSetAttribute(gemm_kernel, cudaFuncAttributeMaxDynamicSharedMemorySize, DYN_SMEM);
    gemm_kernel<<<dim3(N / BN, M / BM), 256, DYN_SMEM>>>(out, bias);
}

// round 5
// speedup vs baseline: 1.5134x; 1.0436x over previous
#include <cuda_runtime.h>
#include <cuda_fp16.h>
#include <cstdint>
#include <cstddef>

// Problem sizes
static constexpr int M = 8192;   // tokens
static constexpr int K = 4096;   // in features
static constexpr int N = 4096;   // out features

// GEMM tiling: CTA 256x128x64, 16 warps (4 M x 4 N), warp tile 64x32.
// occ=1 but 4 warps/SMSP; L2 tile traffic same as 128x256 config (3.2 GB).
static constexpr int BM = 256;
static constexpr int BN = 128;
static constexpr int BK = 64;                    // 64 fp16 = 128 B per row
static constexpr int NIT = K / BK;               // 64
static constexpr int STAGES = 4;
static constexpr int A_STAGE_BYTES = BM * 128;   // 32 KB
static constexpr int B_STAGE_BYTES = BN * 128;   // 16 KB
static constexpr int STAGE_BYTES = A_STAGE_BYTES + B_STAGE_BYTES;  // 48 KB
static constexpr int DYN_SMEM = 1024 + STAGES * STAGE_BYTES;       // ~193 KB

// Scratch (static device arrays are allowed; cudaMalloc is not)
__device__ __half g_A[(size_t)M * K];   // sign(x) as fp16, [M,K] row-major
__device__ __half g_B[(size_t)N * K];   // W^T as fp16,     [N,K] row-major (= col-major B)

// ---------------- PTX helpers (baseline sm_103, no 'a' features) ----------------
__device__ __forceinline__ uint32_t smem_u32(const void* p) {
    uint32_t a;
    asm("{ .reg .u64 t; cvta.to.shared.u64 t, %1; cvt.u32.u64 %0, t; }" : "=r"(a) : "l"(p));
    return a;
}
__device__ __forceinline__ void cp_async16(uint32_t s, const void* g) {
    asm volatile("cp.async.cg.shared.global [%0], [%1], 16;" :: "r"(s), "l"(g));
}
__device__ __forceinline__ void cp_commit() {
    asm volatile("cp.async.commit_group;" ::: "memory");
}
template <int NWAIT>
__device__ __forceinline__ void cp_wait() {
    asm volatile("cp.async.wait_group %0;" :: "n"(NWAIT) : "memory");
}
__device__ __forceinline__ void ldsm_x4(uint32_t& r0, uint32_t& r1, uint32_t& r2, uint32_t& r3,
                                        uint32_t addr) {
    asm volatile("ldmatrix.sync.aligned.m8n8.x4.shared.b16 {%0,%1,%2,%3}, [%4];"
                 : "=r"(r0), "=r"(r1), "=r"(r2), "=r"(r3) : "r"(addr));
}
__device__ __forceinline__ void mma16816(float& d0, float& d1, float& d2, float& d3,
                                         uint32_t a0, uint32_t a1, uint32_t a2, uint32_t a3,
                                         uint32_t b0, uint32_t b1) {
    asm volatile(
        "mma.sync.aligned.m16n8k16.row.col.f32.f16.f16.f32 "
        "{%0,%1,%2,%3}, {%4,%5,%6,%7}, {%8,%9}, {%0,%1,%2,%3};"
        : "+f"(d0), "+f"(d1), "+f"(d2), "+f"(d3)
        : "r"(a0), "r"(a1), "r"(a2), "r"(a3), "r"(b0), "r"(b1));
}
// SW128-style swizzle: XOR 16B-chunk index with (row & 7)
__device__ __forceinline__ uint32_t swz(uint32_t off) { return off ^ ((off >> 3) & 0x70); }

// ---------------- Kernel 1: binarize x -> fp16 {+1,-1} ----------------
__global__ void binarize_kernel(const float4* __restrict__ x4, int n4) {
    int i = blockIdx.x * blockDim.x + threadIdx.x;
    const int stride = gridDim.x * blockDim.x;
    const __half one = __float2half_rn(1.0f);
    const __half neg = __float2half_rn(-1.0f);
    uint2* a8 = reinterpret_cast<uint2*>(g_A);
    for (; i < n4; i += stride) {
        float4 v = x4[i];
        __half2 h0 = __halves2half2(v.x > 0.0f ? one : neg, v.y > 0.0f ? one : neg);
        __half2 h1 = __halves2half2(v.z > 0.0f ? one : neg, v.w > 0.0f ? one : neg);
        uint2 pk;
        pk.x = *reinterpret_cast<uint32_t*>(&h0);
        pk.y = *reinterpret_cast<uint32_t*>(&h1);
        a8[i] = pk;
    }
}

// ---------------- Kernel 2: W [K,N] fp32 -> g_B [N,K] fp16 (transpose+convert) ----------------
__global__ void wconv_kernel(const float* __restrict__ W) {
    __shared__ float t[32][33];
    const int n0 = blockIdx.x * 32;
    const int k0 = blockIdx.y * 32;
    const int tx = threadIdx.x, ty = threadIdx.y;   // 32 x 8
#pragma unroll
    for (int r = 0; r < 4; ++r)
        t[ty + 8 * r][tx] = W[(size_t)(k0 + ty + 8 * r) * N + n0 + tx];
    __syncthreads();
#pragma unroll
    for (int r = 0; r < 4; ++r)
        g_B[(size_t)(n0 + ty + 8 * r) * K + k0 + tx] = __float2half_rn(t[tx][ty + 8 * r]);
}

// ---------------- Kernel 3: mma.sync fp16 GEMM + bias ----------------
__device__ __forceinline__ void load_stage(uint32_t tile0, int m0, int n0, int k_it, int slot,
                                           int tid) {
    const int k0 = k_it * BK;
    const uint32_t sa = tile0 + slot * STAGE_BYTES;
    const uint32_t sbm = sa + A_STAGE_BYTES;
    // A: 256 rows x 8 chunks = 2048; B: 128 rows x 8 chunks = 1024; 3072 / 512 thr = 6 each
#pragma unroll
    for (int c = tid; c < 3072; c += 512) {
        if (c < 2048) {
            const int r = c >> 3, j = c & 7;
            cp_async16(sa + swz((uint32_t)(r * 128 + j * 16)),
                       g_A + (((size_t)(m0 + r)) << 12) + k0 + (j << 3));
        } else {
            const int c2 = c - 2048;
            const int r = c2 >> 3, j = c2 & 7;
            cp_async16(sbm + swz((uint32_t)(r * 128 + j * 16)),
                       g_B + (((size_t)(n0 + r)) << 12) + k0 + (j << 3));
        }
    }
}

__global__ void __launch_bounds__(512, 1) gemm_kernel(float* __restrict__ out,
                                                      const float* __restrict__ bias) {
    extern __shared__ char smem[];
    const uint32_t tile0 = (smem_u32(smem) + 1023) & ~1023u;
    const int tid = threadIdx.x;
    const int wid = tid >> 5;
    const int lane = tid & 31;
    const int m0 = blockIdx.y * BM;
    const int n0 = blockIdx.x * BN;
    const int warp_m = wid & 3;        // 0..3 -> 64 rows each
    const int warp_n = wid >> 2;       // 0..3 -> 32 cols each

    // Swizzled ldmatrix offsets (kk=0).
    // A row-major m16k16 x4: t0-7 m0-7@k0, t8-15 m8-15@k0, t16-23 m0-7@+16B, t24-31 m8-15@+16B
    uint32_t aoff[4];
#pragma unroll
    for (int mi = 0; mi < 4; ++mi) {
        const int row = warp_m * 64 + mi * 16 + (lane & 15);
        aoff[mi] = swz((uint32_t)(row * 128) + (uint32_t)((lane >> 4) << 4));
    }
    // B col-major n16k16 x4: t0-7 n0-7@k0, t8-15 n0-7@+16B, t16-23 n8-15@k0, t24-31 n8-15@+16B
    uint32_t boff[2];
#pragma unroll
    for (int pj = 0; pj < 2; ++pj) {
        const int row = warp_n * 32 + pj * 16 + (lane & 7) + ((lane >> 4) << 3);
        boff[pj] = swz((uint32_t)(row * 128) + (uint32_t)(((lane >> 3) & 1) << 4));
    }

    float acc[4][4][4];   // [mi][nj][c]
#pragma unroll
    for (int mi = 0; mi < 4; ++mi)
#pragma unroll
        for (int nj = 0; nj < 4; ++nj)
#pragma unroll
            for (int c = 0; c < 4; ++c) acc[mi][nj][c] = 0.0f;

    // Prologue: fill stages 0..2
#pragma unroll
    for (int p = 0; p < STAGES - 1; ++p) {
        load_stage(tile0, m0, n0, p, p, tid);
        cp_commit();
    }

    for (int it = 0; it < NIT; ++it) {
        cp_wait<STAGES - 2>();
        __syncthreads();

        // Issue next stage's loads first so they overlap this iter's compute.
        if (it + STAGES - 1 < NIT)
            load_stage(tile0, m0, n0, it + STAGES - 1, (it + STAGES - 1) % STAGES, tid);
        cp_commit();

        const uint32_t sa = tile0 + (it % STAGES) * STAGE_BYTES;
        const uint32_t sbm = sa + A_STAGE_BYTES;

#pragma unroll
        for (int kk = 0; kk < 4; ++kk) {
            const uint32_t kx = (uint32_t)(kk << 5);
            uint32_t a[4][4];
#pragma unroll
            for (int mi = 0; mi < 4; ++mi)
                ldsm_x4(a[mi][0], a[mi][1], a[mi][2], a[mi][3], sa + (aoff[mi] ^ kx));
            uint32_t b[4][2];
#pragma unroll
            for (int pj = 0; pj < 2; ++pj) {
                uint32_t r0, r1, r2, r3;
                ldsm_x4(r0, r1, r2, r3, sbm + (boff[pj] ^ kx));
                b[pj * 2 + 0][0] = r0; b[pj * 2 + 0][1] = r1;
                b[pj * 2 + 1][0] = r2; b[pj * 2 + 1][1] = r3;
            }
#pragma unroll
            for (int mi = 0; mi < 4; ++mi)
#pragma unroll
                for (int nj = 0; nj < 4; ++nj)
                    mma16816(acc[mi][nj][0], acc[mi][nj][1], acc[mi][nj][2], acc[mi][nj][3],
                             a[mi][0], a[mi][1], a[mi][2], a[mi][3],
                             b[nj][0], b[nj][1]);
        }
    }

    // Epilogue
    const int g = lane >> 2, tg = lane & 3;
#pragma unroll
    for (int mi = 0; mi < 4; ++mi) {
        const int r0 = m0 + warp_m * 64 + mi * 16 + g;
        float* o0 = out + (size_t)r0 * N;
        float* o1 = out + (size_t)(r0 + 8) * N;
#pragma unroll
        for (int nj = 0; nj < 4; ++nj) {
            const int col = n0 + warp_n * 32 + nj * 8 + tg * 2;
            const float b0 = __ldg(bias + col);
            const float b1 = __ldg(bias + col + 1);
            float2 v0 = make_float2(acc[mi][nj][0] + b0, acc[mi][nj][1] + b1);
            float2 v1 = make_float2(acc[mi][nj][2] + b0, acc[mi][nj][3] + b1);
            *reinterpret_cast<float2*>(o0 + col) = v0;
            *reinterpret_cast<float2*>(o1 + col) = v1;
        }
    }
}

// ---------------- launch ----------------
extern "C" void kernel_launch(void* const* d_in, const int* in_sizes, int n_in,
                              void* d_out, int out_size) {
    const float* x    = (const float*)d_in[0];
    const float* W    = (const float*)d_in[1];
    const float* bias = (const float*)d_in[2];
    float* out = (float*)d_out;

    binarize_kernel<<<4096, 256>>>((const float4*)x, (M * K) / 4);
    wconv_kernel<<<dim3(N / 32, K / 32), dim3(32, 8)>>>(W);

    cudaFuncSetAttribute(gemm_kernel, cudaFuncAttributeMaxDynamicSharedMemorySize, DYN_SMEM);
    gemm_kernel<<<dim3(N / BN, M / BM), 512, DYN_SMEM>>>(out, bias);
}

// round 6
// speedup vs baseline: 1.5267x; 1.0087x over previous
#include <cuda_runtime.h>
#include <cuda_fp16.h>
#include <cstdint>
#include <cstddef>

// Problem sizes
static constexpr int M = 8192;   // tokens
static constexpr int K = 4096;   // in features
static constexpr int N = 4096;   // out features

// GEMM tiling: CTA 256x128x64, 16 warps (4 M x 4 N), warp tile 64x32.
static constexpr int BM = 256;
static constexpr int BN = 128;
static constexpr int BK = 64;                    // 64 fp16 = 128 B per row
static constexpr int NIT = K / BK;               // 64
static constexpr int STAGES = 4;
static constexpr int A_STAGE_BYTES = BM * 128;   // 32 KB
static constexpr int B_STAGE_BYTES = BN * 128;   // 16 KB
static constexpr int STAGE_BYTES = A_STAGE_BYTES + B_STAGE_BYTES;  // 48 KB
static constexpr int DYN_SMEM = 1024 + STAGES * STAGE_BYTES;       // ~193 KB

// Scratch (static device arrays are allowed; cudaMalloc is not)
__device__ __half g_A[(size_t)M * K];   // sign(x) as fp16, [M,K] row-major
__device__ __half g_B[(size_t)N * K];   // W^T as fp16,     [N,K] row-major (= col-major B)

// ---------------- PTX helpers (baseline sm_103, no 'a' features) ----------------
__device__ __forceinline__ uint32_t smem_u32(const void* p) {
    uint32_t a;
    asm("{ .reg .u64 t; cvta.to.shared.u64 t, %1; cvt.u32.u64 %0, t; }" : "=r"(a) : "l"(p));
    return a;
}
__device__ __forceinline__ void cp_async16(uint32_t s, const void* g) {
    asm volatile("cp.async.cg.shared.global [%0], [%1], 16;" :: "r"(s), "l"(g));
}
__device__ __forceinline__ void cp_commit() {
    asm volatile("cp.async.commit_group;" ::: "memory");
}
template <int NWAIT>
__device__ __forceinline__ void cp_wait() {
    asm volatile("cp.async.wait_group %0;" :: "n"(NWAIT) : "memory");
}
__device__ __forceinline__ void ldsm_x4(uint32_t& r0, uint32_t& r1, uint32_t& r2, uint32_t& r3,
                                        uint32_t addr) {
    asm volatile("ldmatrix.sync.aligned.m8n8.x4.shared.b16 {%0,%1,%2,%3}, [%4];"
                 : "=r"(r0), "=r"(r1), "=r"(r2), "=r"(r3) : "r"(addr));
}
__device__ __forceinline__ void mma16816(float& d0, float& d1, float& d2, float& d3,
                                         uint32_t a0, uint32_t a1, uint32_t a2, uint32_t a3,
                                         uint32_t b0, uint32_t b1) {
    asm volatile(
        "mma.sync.aligned.m16n8k16.row.col.f32.f16.f16.f32 "
        "{%0,%1,%2,%3}, {%4,%5,%6,%7}, {%8,%9}, {%0,%1,%2,%3};"
        : "+f"(d0), "+f"(d1), "+f"(d2), "+f"(d3)
        : "r"(a0), "r"(a1), "r"(a2), "r"(a3), "r"(b0), "r"(b1));
}
// SW128-style swizzle: XOR 16B-chunk index with (row & 7)
__device__ __forceinline__ uint32_t swz(uint32_t off) { return off ^ ((off >> 3) & 0x70); }

// ---------------- Kernel 1: binarize x -> fp16 {+1,-1} ----------------
__global__ void binarize_kernel(const float4* __restrict__ x4, int n4) {
    int i = blockIdx.x * blockDim.x + threadIdx.x;
    const int stride = gridDim.x * blockDim.x;
    const __half one = __float2half_rn(1.0f);
    const __half neg = __float2half_rn(-1.0f);
    uint2* a8 = reinterpret_cast<uint2*>(g_A);
    for (; i < n4; i += stride) {
        float4 v = x4[i];
        __half2 h0 = __halves2half2(v.x > 0.0f ? one : neg, v.y > 0.0f ? one : neg);
        __half2 h1 = __halves2half2(v.z > 0.0f ? one : neg, v.w > 0.0f ? one : neg);
        uint2 pk;
        pk.x = *reinterpret_cast<uint32_t*>(&h0);
        pk.y = *reinterpret_cast<uint32_t*>(&h1);
        a8[i] = pk;
    }
}

// ---------------- Kernel 2: W [K,N] fp32 -> g_B [N,K] fp16 (transpose+convert) ----------------
__global__ void wconv_kernel(const float* __restrict__ W) {
    __shared__ float t[32][33];
    const int n0 = blockIdx.x * 32;
    const int k0 = blockIdx.y * 32;
    const int tx = threadIdx.x, ty = threadIdx.y;   // 32 x 8
#pragma unroll
    for (int r = 0; r < 4; ++r)
        t[ty + 8 * r][tx] = W[(size_t)(k0 + ty + 8 * r) * N + n0 + tx];
    __syncthreads();
#pragma unroll
    for (int r = 0; r < 4; ++r)
        g_B[(size_t)(n0 + ty + 8 * r) * K + k0 + tx] = __float2half_rn(t[tx][ty + 8 * r]);
}

// ---------------- Kernel 3: mma.sync fp16 GEMM + bias ----------------
__device__ __forceinline__ void load_stage(uint32_t tile0, int m0, int n0, int k_it, int slot,
                                           int tid) {
    const int k0 = k_it * BK;
    const uint32_t sa = tile0 + slot * STAGE_BYTES;
    const uint32_t sbm = sa + A_STAGE_BYTES;
#pragma unroll
    for (int c = tid; c < 3072; c += 512) {
        if (c < 2048) {
            const int r = c >> 3, j = c & 7;
            cp_async16(sa + swz((uint32_t)(r * 128 + j * 16)),
                       g_A + (((size_t)(m0 + r)) << 12) + k0 + (j << 3));
        } else {
            const int c2 = c - 2048;
            const int r = c2 >> 3, j = c2 & 7;
            cp_async16(sbm + swz((uint32_t)(r * 128 + j * 16)),
                       g_B + (((size_t)(n0 + r)) << 12) + k0 + (j << 3));
        }
    }
}

__global__ void __launch_bounds__(512, 1) gemm_kernel(float* __restrict__ out,
                                                      const float* __restrict__ bias) {
    extern __shared__ char smem[];
    const uint32_t tile0 = (smem_u32(smem) + 1023) & ~1023u;
    const int tid = threadIdx.x;
    const int wid = tid >> 5;
    const int lane = tid & 31;
    const int m0 = blockIdx.y * BM;
    const int n0 = blockIdx.x * BN;
    const int warp_m = wid & 3;        // 0..3 -> 64 rows each
    const int warp_n = wid >> 2;       // 0..3 -> 32 cols each

    // Swizzled ldmatrix offsets (kk=0).
    uint32_t aoff[4];
#pragma unroll
    for (int mi = 0; mi < 4; ++mi) {
        const int row = warp_m * 64 + mi * 16 + (lane & 15);
        aoff[mi] = swz((uint32_t)(row * 128) + (uint32_t)((lane >> 4) << 4));
    }
    uint32_t boff[2];
#pragma unroll
    for (int pj = 0; pj < 2; ++pj) {
        const int row = warp_n * 32 + pj * 16 + (lane & 7) + ((lane >> 4) << 3);
        boff[pj] = swz((uint32_t)(row * 128) + (uint32_t)(((lane >> 3) & 1) << 4));
    }

    float acc[4][4][4];   // [mi][nj][c]
#pragma unroll
    for (int mi = 0; mi < 4; ++mi)
#pragma unroll
        for (int nj = 0; nj < 4; ++nj)
#pragma unroll
            for (int c = 0; c < 4; ++c) acc[mi][nj][c] = 0.0f;

    // Prologue: fill stages 0..2
#pragma unroll
    for (int p = 0; p < STAGES - 1; ++p) {
        load_stage(tile0, m0, n0, p, p, tid);
        cp_commit();
    }

    for (int it = 0; it < NIT; ++it) {
        cp_wait<STAGES - 2>();
        __syncthreads();

        // Issue next stage's loads first so they overlap this iter's compute.
        if (it + STAGES - 1 < NIT)
            load_stage(tile0, m0, n0, it + STAGES - 1, (it + STAGES - 1) % STAGES, tid);
        cp_commit();

        const uint32_t sa = tile0 + (it % STAGES) * STAGE_BYTES;
        const uint32_t sbm = sa + A_STAGE_BYTES;

        // Software-pipelined fragment flow:
        //   B double-buffered across kk (16 regs), A rotated across mi (8 regs).
        uint32_t bcur[4][2], bnxt[4][2];
        {
            uint32_t r0, r1, r2, r3;
            ldsm_x4(r0, r1, r2, r3, sbm + boff[0]);
            bcur[0][0] = r0; bcur[0][1] = r1; bcur[1][0] = r2; bcur[1][1] = r3;
            ldsm_x4(r0, r1, r2, r3, sbm + boff[1]);
            bcur[2][0] = r0; bcur[2][1] = r1; bcur[3][0] = r2; bcur[3][1] = r3;
        }
        uint32_t acur[4], anxt[4];
        ldsm_x4(acur[0], acur[1], acur[2], acur[3], sa + aoff[0]);

#pragma unroll
        for (int kk = 0; kk < 4; ++kk) {
            const uint32_t kx = (uint32_t)(kk << 5);
            const uint32_t kxn = (uint32_t)((kk + 1) << 5);
            if (kk < 3) {   // prefetch next kk's B
                uint32_t r0, r1, r2, r3;
                ldsm_x4(r0, r1, r2, r3, sbm + (boff[0] ^ kxn));
                bnxt[0][0] = r0; bnxt[0][1] = r1; bnxt[1][0] = r2; bnxt[1][1] = r3;
                ldsm_x4(r0, r1, r2, r3, sbm + (boff[1] ^ kxn));
                bnxt[2][0] = r0; bnxt[2][1] = r1; bnxt[3][0] = r2; bnxt[3][1] = r3;
            }
#pragma unroll
            for (int mi = 0; mi < 4; ++mi) {
                if (mi < 3)
                    ldsm_x4(anxt[0], anxt[1], anxt[2], anxt[3], sa + (aoff[mi + 1] ^ kx));
                else if (kk < 3)
                    ldsm_x4(anxt[0], anxt[1], anxt[2], anxt[3], sa + (aoff[0] ^ kxn));
#pragma unroll
                for (int nj = 0; nj < 4; ++nj)
                    mma16816(acc[mi][nj][0], acc[mi][nj][1], acc[mi][nj][2], acc[mi][nj][3],
                             acur[0], acur[1], acur[2], acur[3],
                             bcur[nj][0], bcur[nj][1]);
#pragma unroll
                for (int q = 0; q < 4; ++q) acur[q] = anxt[q];
            }
            if (kk < 3) {
#pragma unroll
                for (int nj = 0; nj < 4; ++nj) {
                    bcur[nj][0] = bnxt[nj][0];
                    bcur[nj][1] = bnxt[nj][1];
                }
            }
        }
    }

    // Epilogue
    const int g = lane >> 2, tg = lane & 3;
#pragma unroll
    for (int mi = 0; mi < 4; ++mi) {
        const int r0 = m0 + warp_m * 64 + mi * 16 + g;
        float* o0 = out + (size_t)r0 * N;
        float* o1 = out + (size_t)(r0 + 8) * N;
#pragma unroll
        for (int nj = 0; nj < 4; ++nj) {
            const int col = n0 + warp_n * 32 + nj * 8 + tg * 2;
            const float b0 = __ldg(bias + col);
            const float b1 = __ldg(bias + col + 1);
            float2 v0 = make_float2(acc[mi][nj][0] + b0, acc[mi][nj][1] + b1);
            float2 v1 = make_float2(acc[mi][nj][2] + b0, acc[mi][nj][3] + b1);
            *reinterpret_cast<float2*>(o0 + col) = v0;
            *reinterpret_cast<float2*>(o1 + col) = v1;
        }
    }
}

// ---------------- launch ----------------
extern "C" void kernel_launch(void* const* d_in, const int* in_sizes, int n_in,
                              void* d_out, int out_size) {
    const float* x    = (const float*)d_in[0];
    const float* W    = (const float*)d_in[1];
    const float* bias = (const float*)d_in[2];
    float* out = (float*)d_out;

    binarize_kernel<<<4096, 256>>>((const float4*)x, (M * K) / 4);
    wconv_kernel<<<dim3(N / 32, K / 32), dim3(32, 8)>>>(W);

    cudaFuncSetAttribute(gemm_kernel, cudaFuncAttributeMaxDynamicSharedMemorySize, DYN_SMEM);
    gemm_kernel<<<dim3(N / BN, M / BM), 512, DYN_SMEM>>>(out, bias);
}